// round 17
// baseline (speedup 1.0000x reference)
#include <cuda_runtime.h>
#include <cuda_bf16.h>
#include <cuda_fp16.h>
#include <cstdint>
#include <math.h>

// Problem constants
constexpr int M_ROWS = 65536;   // B*S*G
constexpr int N_V    = 320;
constexpr int K_D    = 384;
constexpr int OUT_D  = 768;
constexpr int GV     = 640;
constexpr float EPS_G  = 1e-10f;
constexpr float MARGIN = 0.43f;   // bf16 GEMM + fast-log + fp16 logits store

// Device-global scratch (no allocation allowed)
__device__ __half        g_logits[(size_t)M_ROWS * N_V]; // 42MB
__device__ __nv_bfloat16 g_Wt_bf16[N_V * K_D];     // W_logits^T bf16
__device__ float         g_Wt_f32 [N_V * K_D];     // W_logits^T fp32
__device__ float         g_E[GV * OUT_D];          // codebook@W_out fused table

__device__ __forceinline__ float gumbel_acc(float u) {
    return -logf(-logf(u + EPS_G) + EPS_G);
}
__device__ __forceinline__ float gumbel_fast(float u) {
    if (u > 0.999f) return gumbel_acc(u);   // rare accurate path
    float w = -__logf(u + EPS_G) + EPS_G;
    return -__logf(w);
}
__device__ __forceinline__ void two_sum(float& s, float& c, float v) {
    float t  = s + v;
    float bv = t - s;
    float err = (s - (t - bv)) + (v - bv);
    s = t; c += err;
}

__device__ __forceinline__ void ldsm_x4(uint32_t* r, const void* p) {
    uint32_t addr = (uint32_t)__cvta_generic_to_shared(p);
    asm volatile("ldmatrix.sync.aligned.m8n8.x4.shared.b16 {%0,%1,%2,%3}, [%4];\n"
        : "=r"(r[0]), "=r"(r[1]), "=r"(r[2]), "=r"(r[3]) : "r"(addr));
}
__device__ __forceinline__ void mma_bf16(float* c, const uint32_t* a, const uint32_t* b) {
    asm volatile("mma.sync.aligned.m16n8k16.row.col.f32.bf16.bf16.f32 "
        "{%0,%1,%2,%3}, {%4,%5,%6,%7}, {%8,%9}, {%0,%1,%2,%3};\n"
        : "+f"(c[0]), "+f"(c[1]), "+f"(c[2]), "+f"(c[3])
        : "r"(a[0]), "r"(a[1]), "r"(a[2]), "r"(a[3]), "r"(b[0]), "r"(b[1]));
}
__device__ __forceinline__ void cp16(void* dst_smem, const void* src) {
    uint32_t d = (uint32_t)__cvta_generic_to_shared(dst_smem);
    asm volatile("cp.async.cg.shared.global [%0], [%1], 16;\n" :: "r"(d), "l"(src));
}
#define CP_COMMIT() asm volatile("cp.async.commit_group;\n")
#define CP_WAIT1()  asm volatile("cp.async.wait_group 1;\n")

__device__ __forceinline__ uint32_t pack_bf16x2(float lo, float hi) {
    __nv_bfloat162 p = __floats2bfloat162_rn(lo, hi);
    return *reinterpret_cast<uint32_t*>(&p);
}

// ---------------------------------------------------------------------------
// Prep (small now): b0..479 = W^T (bf16+fp32); b480..719 = E GEMM
// ---------------------------------------------------------------------------
__global__ __launch_bounds__(256) void prep_kernel(
    const float* __restrict__ W, const float* __restrict__ CB,
    const float* __restrict__ Wout)
{
    __shared__ float As2[32][17];
    __shared__ float Bs2[16][68];
    const int b = blockIdx.x;
    const int t = threadIdx.x;

    if (b < 480) {
        int i = b * 256 + t;                 // covers 384*320 exactly
        int k = i / N_V, n = i % N_V;
        float v = W[i];
        g_Wt_f32 [n * K_D + k] = v;
        g_Wt_bf16[n * K_D + k] = __float2bfloat16(v);
    } else {
        const int eb = b - 480;              // 0..239
        const int o0  = (eb % 12) * 64;
        const int gv0 = (eb / 12) * 32;
        const int ty = t >> 4, tx = t & 15;
        const int goff = (gv0 >= 320) ? 384 : 0;
        float acc0[4] = {0.f,0.f,0.f,0.f}, acc1[4] = {0.f,0.f,0.f,0.f};

        for (int k0 = 0; k0 < K_D; k0 += 16) {
            #pragma unroll
            for (int i = 0; i < 2; ++i) {
                int idx = t + i * 256;
                int r = idx >> 4, c = idx & 15;
                As2[r][c] = CB[(size_t)(gv0 + r) * K_D + k0 + c];
            }
            #pragma unroll
            for (int i = 0; i < 4; ++i) {
                int idx = t + i * 256;
                int r = idx >> 6, c = idx & 63;
                Bs2[r][c] = Wout[(size_t)(goff + k0 + r) * OUT_D + o0 + c];
            }
            __syncthreads();
            #pragma unroll
            for (int k = 0; k < 16; ++k) {
                float a0 = As2[ty][k], a1 = As2[ty + 16][k];
                #pragma unroll
                for (int j = 0; j < 4; ++j) {
                    float bb = Bs2[k][tx * 4 + j];
                    acc0[j] = fmaf(a0, bb, acc0[j]);
                    acc1[j] = fmaf(a1, bb, acc1[j]);
                }
            }
            __syncthreads();
        }
        #pragma unroll
        for (int j = 0; j < 4; ++j) {
            g_E[(size_t)(gv0 + ty)      * OUT_D + o0 + tx * 4 + j] = acc0[j];
            g_E[(size_t)(gv0 + ty + 16) * OUT_D + o0 + tx * 4 + j] = acc1[j];
        }
    }
}

// ---------------------------------------------------------------------------
// GEMM kernel: BM=64, 512 thr, 3-stage cp.async. A = fp32 direct from z;
//   fragments assembled via LDS + cvt (bit-identical to bf16 pre-convert).
// ---------------------------------------------------------------------------
constexpr int AZ_PITCH    = 36;                                // fp32 per A row
constexpr int STAGE_BYTES = 64 * AZ_PITCH * 4 + 320 * 40 * 2;  // 9216+25600=34816
constexpr int SMEM_G      = 3 * STAGE_BYTES;                   // 104448

__global__ __launch_bounds__(512, 1) void gemm_kernel(const float* __restrict__ z)
{
    extern __shared__ __align__(16) unsigned char sm[];
    const int tid  = threadIdx.x;
    const int lane = tid & 31, wid = tid >> 5;
    const int warp_m = wid & 3, warp_n = wid >> 2;
    const int row0 = blockIdx.x * 64;

    float acc[10][4];
    #pragma unroll
    for (int t = 0; t < 10; ++t)
        #pragma unroll
        for (int j = 0; j < 4; ++j) acc[t][j] = 0.f;

    auto Az = [&](int s) { return (float*)(sm + s * STAGE_BYTES); };
    auto Ws = [&](int s) { return (__nv_bfloat16*)(sm + s * STAGE_BYTES + 64 * AZ_PITCH * 4); };

    auto issue = [&](int kt) {
        if (kt < 12) {
            const int k0 = kt * 32, s = kt % 3;
            {   // A tile fp32: 64 rows x 32 floats = 512 x 16B, one per thread
                int r = tid >> 3, c4 = (tid & 7) * 4;
                cp16(Az(s) + r * AZ_PITCH + c4, &z[(size_t)(row0 + r) * K_D + k0 + c4]);
            }
            #pragma unroll
            for (int i = 0; i < 3; ++i) {   // W tile: 320 x 32 bf16 = 1280 x 16B
                int idx = tid + i * 512;
                if (idx < 1280) {
                    int r = idx >> 2, c8 = (idx & 3) * 8;
                    cp16(Ws(s) + r * 40 + c8, &g_Wt_bf16[(size_t)r * K_D + k0 + c8]);
                }
            }
        }
        CP_COMMIT();
    };
    issue(0); issue(1);

    const int li = lane & 7, lj = lane >> 3;
    const int aq = lane >> 2, ap = lane & 3;
    for (int kt = 0; kt < 12; ++kt) {
        CP_WAIT1();
        __syncthreads();
        issue(kt + 2);
        const float* A = Az(kt % 3);
        const __nv_bfloat16* W = Ws(kt % 3);
        #pragma unroll
        for (int ks = 0; ks < 2; ++ks) {
            const int kk = ks * 16;
            // A fragment m16k16 from fp32 smem -> bf16x2 regs (rn rounding)
            uint32_t a[4];
            {
                const float* base = &A[(warp_m * 16 + aq) * AZ_PITCH + kk + ap * 2];
                float2 f0 = *reinterpret_cast<const float2*>(base);
                float2 f1 = *reinterpret_cast<const float2*>(base + 8 * AZ_PITCH);
                float2 f2 = *reinterpret_cast<const float2*>(base + 8);
                float2 f3 = *reinterpret_cast<const float2*>(base + 8 * AZ_PITCH + 8);
                a[0] = pack_bf16x2(f0.x, f0.y);
                a[1] = pack_bf16x2(f1.x, f1.y);
                a[2] = pack_bf16x2(f2.x, f2.y);
                a[3] = pack_bf16x2(f3.x, f3.y);
            }
            #pragma unroll
            for (int p = 0; p < 5; ++p) {
                uint32_t b[4];
                int r = warp_n * 80 + p * 16 + (lj >> 1) * 8 + li;
                int c = kk + (lj & 1) * 8;
                ldsm_x4(b, &W[r * 40 + c]);
                mma_bf16(acc[2 * p],     a, b);
                mma_bf16(acc[2 * p + 1], a, b + 2);
            }
        }
    }

    // store logits fp16
    const int gid = lane >> 2, tig = lane & 3;
    const int r1 = warp_m * 16 + gid;
    const int r2 = r1 + 8;
    #pragma unroll
    for (int t = 0; t < 10; ++t) {
        const int col = warp_n * 80 + t * 8 + 2 * tig;
        __half2 lo = __floats2half2_rn(acc[t][0], acc[t][1]);
        __half2 hi = __floats2half2_rn(acc[t][2], acc[t][3]);
        *reinterpret_cast<__half2*>(&g_logits[(size_t)(row0 + r1) * N_V + col]) = lo;
        *reinterpret_cast<__half2*>(&g_logits[(size_t)(row0 + r2) * N_V + col]) = hi;
    }
}

// ---------------------------------------------------------------------------
// Epilogue kernel (unchanged from R16): 256 thr, high occupancy.
// ---------------------------------------------------------------------------
__global__ __launch_bounds__(256) void ep_kernel(
    const float* __restrict__ z, const float* __restrict__ noise,
    const float* __restrict__ blog, const float* __restrict__ bout,
    float* __restrict__ out)
{
    __shared__ float blogS[N_V];
    __shared__ int   idxs[64];
    const int tid  = threadIdx.x;
    const int lane = tid & 31, wid = tid >> 5;
    const int row0 = blockIdx.x * 64;

    for (int i = tid; i < N_V; i += 256) blogS[i] = blog[i];
    __syncthreads();

    #pragma unroll 1
    for (int rr = 0; rr < 8; ++rr) {
        const int rl = wid * 8 + rr;
        const size_t gRow = row0 + rl;

        const int c0 = lane * 10;
        float l[10];
        {
            const __half2* Lp = reinterpret_cast<const __half2*>(
                &g_logits[gRow * N_V + c0]);
            #pragma unroll
            for (int j = 0; j < 5; ++j) {
                float2 f = __half22float2(Lp[j]);
                l[2*j] = f.x; l[2*j+1] = f.y;
            }
        }
        float u[10];
        {
            const float2* Np = reinterpret_cast<const float2*>(&noise[gRow * N_V + c0]);
            #pragma unroll
            for (int j = 0; j < 5; ++j) {
                float2 f = Np[j];
                u[2*j] = f.x; u[2*j+1] = f.y;
            }
        }
        float v[10];
        float best = -1e30f; int bc = 0;
        #pragma unroll
        for (int j = 0; j < 10; ++j) {
            v[j] = l[j] + blogS[c0 + j] + gumbel_fast(u[j]);
            if (v[j] > best) { best = v[j]; bc = c0 + j; }
        }
        #pragma unroll
        for (int off = 16; off; off >>= 1) {
            float ov = __shfl_xor_sync(0xffffffffu, best, off);
            int   oc = __shfl_xor_sync(0xffffffffu, bc, off);
            if (ov > best || (ov == best && oc < bc)) { best = ov; bc = oc; }
        }
        const float thr = best - MARGIN;
        int cnt = 0;
        #pragma unroll
        for (int j = 0; j < 10; ++j) cnt += (v[j] >= thr) ? 1 : 0;
        #pragma unroll
        for (int off = 16; off; off >>= 1)
            cnt += __shfl_xor_sync(0xffffffffu, cnt, off);

        if (cnt <= 1) {
            if (lane == 0) idxs[rl] = bc;
            continue;
        }
        const float* zr = &z[gRow * K_D];
        float bhi = -1e30f, blo = 0.f; int bbc = 0x7fffffff;
        #pragma unroll 1
        for (int j = 0; j < 10; ++j) {
            unsigned ball = __ballot_sync(0xffffffffu, v[j] >= thr);
            while (ball) {
                int src = __ffs(ball) - 1; ball &= ball - 1;
                int col = src * 10 + j;
                const float* wr = &g_Wt_f32[(size_t)col * K_D];
                float s = 0.f, c = 0.f;
                #pragma unroll
                for (int i = 0; i < 12; ++i) {
                    int k = i * 32 + lane;
                    float a = zr[k], b = wr[k];
                    float p = a * b;
                    float e = fmaf(a, b, -p);
                    two_sum(s, c, p);
                    c += e;
                }
                #pragma unroll
                for (int off = 16; off; off >>= 1) {
                    float so = __shfl_xor_sync(0xffffffffu, s, off);
                    float co = __shfl_xor_sync(0xffffffffu, c, off);
                    two_sum(s, c, so);
                    c += co;
                }
                float uu = __ldg(&noise[gRow * N_V + col]);
                float base = blogS[col] + gumbel_acc(uu);
                two_sum(s, c, base);
                bool gt = (s > bhi) || (s == bhi && (c > blo || (c == blo && col < bbc)));
                if (gt) { bhi = s; blo = c; bbc = col; }
            }
        }
        if (lane == 0) idxs[rl] = bbc;
    }
    __syncthreads();

    // fused output: 32 tokens, out = E[i0] + E[320+i1] + b_out
    {
        const int tl = tid >> 3;            // token 0..31
        const int j0 = tid & 7;
        const int i0 = idxs[2 * tl];
        const int i1 = idxs[2 * tl + 1];
        const float4* e0 = reinterpret_cast<const float4*>(&g_E[(size_t)i0 * OUT_D]);
        const float4* e1 = reinterpret_cast<const float4*>(&g_E[(size_t)(320 + i1) * OUT_D]);
        const float4* b4 = reinterpret_cast<const float4*>(bout);
        float4* o4 = reinterpret_cast<float4*>(&out[(size_t)(row0 / 2 + tl) * OUT_D]);
        #pragma unroll
        for (int c = j0; c < 192; c += 8) {
            float4 a = e0[c], b = e1[c], bb2 = b4[c];
            o4[c] = make_float4(a.x + b.x + bb2.x, a.y + b.y + bb2.y,
                                a.z + b.z + bb2.z, a.w + b.w + bb2.w);
        }
    }
}

// ---------------------------------------------------------------------------
extern "C" void kernel_launch(void* const* d_in, const int* in_sizes, int n_in,
                              void* d_out, int out_size)
{
    const float *z = nullptr, *noise = nullptr, *Wlog = nullptr, *blog = nullptr,
                *CB = nullptr, *Wout = nullptr, *bout = nullptr;
    for (int i = 0; i < n_in; ++i) {
        switch (in_sizes[i]) {
            case 25165824: z     = (const float*)d_in[i]; break;
            case 20971520: noise = (const float*)d_in[i]; break;
            case 122880:   Wlog  = (const float*)d_in[i]; break;
            case 320:      blog  = (const float*)d_in[i]; break;
            case 245760:   CB    = (const float*)d_in[i]; break;
            case 589824:   Wout  = (const float*)d_in[i]; break;
            case 768:      bout  = (const float*)d_in[i]; break;
        }
    }
    float* out = (float*)d_out;

    static bool attr_set = false;
    if (!attr_set) {
        cudaFuncSetAttribute(gemm_kernel,
            cudaFuncAttributeMaxDynamicSharedMemorySize, SMEM_G);
        attr_set = true;
    }

    prep_kernel<<<720, 256>>>(Wlog, CB, Wout);
    gemm_kernel<<<M_ROWS / 64, 512, SMEM_G>>>(z);
    ep_kernel<<<M_ROWS / 64, 256>>>(z, noise, blog, bout, out);
}